// round 1
// baseline (speedup 1.0000x reference)
#include <cuda_runtime.h>
#include <math.h>
#include <stdint.h>

// Problem constants
#define Bn 4
#define Sn 2048
#define Dn 1024
#define Hn 16
#define DKn 64
#define Mn (Bn * Sn)          // 8192 rows
#define OUT_ELEMS ((size_t)Mn * Dn)          // 8,388,608
#define ATTN_ELEMS ((size_t)Bn * Hn * Sn * Sn) // 268,435,456

// Scratch (device globals; no allocations allowed)
__device__ float g_Q[(size_t)Mn * Dn];
__device__ float g_K[(size_t)Mn * Dn];
__device__ float g_V[(size_t)Mn * Dn];
__device__ float g_ctx[(size_t)Mn * Dn];
__device__ float g_m[Bn * Hn * Sn];
__device__ float g_l[Bn * Hn * Sn];

// ---------------------------------------------------------------------------
// Kernel 1: QKV projection GEMM.  X[8192,1024] @ W[1024,1024] -> P[8192,1024]
// Tiles: 64x64 output, K-tile 16, 256 threads, 4x4 per thread micro-tile.
// grid = (N/64=16, M/64=128, 3)  z selects (q,Wq)/(k,Wk)/(v,Wv)
// ---------------------------------------------------------------------------
__global__ __launch_bounds__(256) void proj_gemm(
    const float* __restrict__ q, const float* __restrict__ k,
    const float* __restrict__ v, const float* __restrict__ Wq,
    const float* __restrict__ Wk, const float* __restrict__ Wv) {
  const int which = blockIdx.z;
  const float* X = (which == 0) ? q : (which == 1) ? k : v;
  const float* W = (which == 0) ? Wq : (which == 1) ? Wk : Wv;
  float* P = (which == 0) ? g_Q : (which == 1) ? g_K : g_V;

  __shared__ __align__(16) float As[16][68];  // transposed: As[k][m]
  __shared__ __align__(16) float Bs[16][68];  // Bs[k][n]

  const int t = threadIdx.x;
  const int tx = t & 15, ty = t >> 4;
  const int m0 = blockIdx.y * 64, n0 = blockIdx.x * 64;

  float acc[4][4] = {};

  for (int k0 = 0; k0 < 1024; k0 += 16) {
    {
      // A tile: 64 rows x 16 k, one float4 along k per thread
      int row = t >> 2;
      int kq = (t & 3) << 2;
      float4 a = *(const float4*)(X + (size_t)(m0 + row) * Dn + k0 + kq);
      As[kq + 0][row] = a.x; As[kq + 1][row] = a.y;
      As[kq + 2][row] = a.z; As[kq + 3][row] = a.w;
      // B tile: 16 rows x 64 n, one float4 along n per thread
      int kr = t >> 4;
      int nq = (t & 15) << 2;
      float4 b = *(const float4*)(W + (size_t)(k0 + kr) * Dn + n0 + nq);
      *(float4*)&Bs[kr][nq] = b;
    }
    __syncthreads();
#pragma unroll
    for (int kk = 0; kk < 16; kk++) {
      float av[4], bv[4];
      *(float4*)av = *(const float4*)&As[kk][ty << 2];
      *(float4*)bv = *(const float4*)&Bs[kk][tx << 2];
#pragma unroll
      for (int ii = 0; ii < 4; ii++)
#pragma unroll
        for (int jj = 0; jj < 4; jj++)
          acc[ii][jj] = fmaf(av[ii], bv[jj], acc[ii][jj]);
    }
    __syncthreads();
  }

#pragma unroll
  for (int ii = 0; ii < 4; ii++) {
    float4 o = make_float4(acc[ii][0], acc[ii][1], acc[ii][2], acc[ii][3]);
    *(float4*)(P + (size_t)(m0 + (ty << 2) + ii) * Dn + n0 + (tx << 2)) = o;
  }
}

// ---------------------------------------------------------------------------
// Kernel 2: flash-style causal attention.
// grid = (S/64=32, H=16, B=4), 256 threads. BM=BN=64, dk=dv=64.
// Produces g_ctx (pre-residual context, layout [B,S,H*64]) and per-row m,l.
// Smem: Qt + shared K/V buffer + P = 3 * 16KB = 48KB static.
// ---------------------------------------------------------------------------
__global__ __launch_bounds__(256) void flash_fwd() {
  const int qb = blockIdx.x, h = blockIdx.y, b = blockIdx.z;
  __shared__ __align__(16) float Qt[64][64];  // Qt[d][i]
  __shared__ __align__(16) float KV[64][64];  // Kt[d][j] then Vs[j][c]
  __shared__ __align__(16) float Ps[64][64];  // P[i][j]

  const int t = threadIdx.x;
  const int tx = t & 15, ty = t >> 4;

  const float* Qg = g_Q + ((size_t)(b * Sn + qb * 64)) * Dn + h * 64;
  for (int idx = t; idx < 1024; idx += 256) {
    int row = idx >> 4;
    int dq = (idx & 15) << 2;
    float4 a = *(const float4*)(Qg + (size_t)row * Dn + dq);
    Qt[dq + 0][row] = a.x; Qt[dq + 1][row] = a.y;
    Qt[dq + 2][row] = a.z; Qt[dq + 3][row] = a.w;
  }

  float m_i[4] = {-1e30f, -1e30f, -1e30f, -1e30f};
  float l_i[4] = {0.f, 0.f, 0.f, 0.f};
  float acc[4][4] = {};
  const float scale = 0.125f;  // 1/sqrt(64)

  for (int kb = 0; kb <= qb; kb++) {
    __syncthreads();  // prev iter done with KV (V) and Ps
    const float* Kg = g_K + ((size_t)(b * Sn + kb * 64)) * Dn + h * 64;
    for (int idx = t; idx < 1024; idx += 256) {
      int row = idx >> 4;
      int dq = (idx & 15) << 2;
      float4 a = *(const float4*)(Kg + (size_t)row * Dn + dq);
      KV[dq + 0][row] = a.x; KV[dq + 1][row] = a.y;
      KV[dq + 2][row] = a.z; KV[dq + 3][row] = a.w;
    }
    __syncthreads();

    float s[4][4] = {};
#pragma unroll 16
    for (int d = 0; d < 64; d++) {
      float qa[4], ka[4];
      *(float4*)qa = *(const float4*)&Qt[d][ty << 2];
      *(float4*)ka = *(const float4*)&KV[d][tx << 2];
#pragma unroll
      for (int ii = 0; ii < 4; ii++)
#pragma unroll
        for (int jj = 0; jj < 4; jj++)
          s[ii][jj] = fmaf(qa[ii], ka[jj], s[ii][jj]);
    }

    const bool diag = (kb == qb);
#pragma unroll
    for (int ii = 0; ii < 4; ii++)
#pragma unroll
      for (int jj = 0; jj < 4; jj++) {
        float sv = s[ii][jj] * scale;
        if (diag && ((tx << 2) + jj) > ((ty << 2) + ii)) sv = -1e30f;
        s[ii][jj] = sv;
      }

    float p[4][4];
#pragma unroll
    for (int ii = 0; ii < 4; ii++) {
      float rmax = fmaxf(fmaxf(s[ii][0], s[ii][1]), fmaxf(s[ii][2], s[ii][3]));
      rmax = fmaxf(rmax, __shfl_xor_sync(0xffffffffu, rmax, 1, 16));
      rmax = fmaxf(rmax, __shfl_xor_sync(0xffffffffu, rmax, 2, 16));
      rmax = fmaxf(rmax, __shfl_xor_sync(0xffffffffu, rmax, 4, 16));
      rmax = fmaxf(rmax, __shfl_xor_sync(0xffffffffu, rmax, 8, 16));
      float mnew = fmaxf(m_i[ii], rmax);
      float alpha = __expf(m_i[ii] - mnew);
      float rs = 0.f;
#pragma unroll
      for (int jj = 0; jj < 4; jj++) {
        p[ii][jj] = __expf(s[ii][jj] - mnew);
        rs += p[ii][jj];
      }
      rs += __shfl_xor_sync(0xffffffffu, rs, 1, 16);
      rs += __shfl_xor_sync(0xffffffffu, rs, 2, 16);
      rs += __shfl_xor_sync(0xffffffffu, rs, 4, 16);
      rs += __shfl_xor_sync(0xffffffffu, rs, 8, 16);
      l_i[ii] = l_i[ii] * alpha + rs;
      m_i[ii] = mnew;
#pragma unroll
      for (int cc = 0; cc < 4; cc++) acc[ii][cc] *= alpha;
    }

    __syncthreads();  // everyone done reading KV as K-tile
    const float* Vg = g_V + ((size_t)(b * Sn + kb * 64)) * Dn + h * 64;
    for (int idx = t; idx < 1024; idx += 256) {
      int row = idx >> 4;
      int dq = (idx & 15) << 2;
      *(float4*)&KV[row][dq] = *(const float4*)(Vg + (size_t)row * Dn + dq);
    }
#pragma unroll
    for (int ii = 0; ii < 4; ii++)
      *(float4*)&Ps[(ty << 2) + ii][tx << 2] =
          make_float4(p[ii][0], p[ii][1], p[ii][2], p[ii][3]);
    __syncthreads();

#pragma unroll 4
    for (int j4 = 0; j4 < 16; j4++) {
      float pr[4][4], vr[4][4];
#pragma unroll
      for (int ii = 0; ii < 4; ii++)
        *(float4*)pr[ii] = *(const float4*)&Ps[(ty << 2) + ii][j4 << 2];
#pragma unroll
      for (int u = 0; u < 4; u++)
        *(float4*)vr[u] = *(const float4*)&KV[(j4 << 2) + u][tx << 2];
#pragma unroll
      for (int u = 0; u < 4; u++)
#pragma unroll
        for (int ii = 0; ii < 4; ii++)
#pragma unroll
          for (int cc = 0; cc < 4; cc++)
            acc[ii][cc] = fmaf(pr[ii][u], vr[u][cc], acc[ii][cc]);
    }
  }

  float* Cg = g_ctx + ((size_t)(b * Sn + qb * 64)) * Dn + h * 64;
#pragma unroll
  for (int ii = 0; ii < 4; ii++) {
    float inv = 1.0f / l_i[ii];
    float4 o = make_float4(acc[ii][0] * inv, acc[ii][1] * inv,
                           acc[ii][2] * inv, acc[ii][3] * inv);
    *(float4*)(Cg + (size_t)((ty << 2) + ii) * Dn + (tx << 2)) = o;
  }
  if (tx == 0) {
    int base = (b * Hn + h) * Sn + qb * 64 + (ty << 2);
#pragma unroll
    for (int ii = 0; ii < 4; ii++) {
      g_m[base + ii] = m_i[ii];
      g_l[base + ii] = l_i[ii];
    }
  }
}

// ---------------------------------------------------------------------------
// Kernel 3: materialize attn[B,H,S,S] = softmax probs (recompute QK^T using
// saved row max m and denominator l). Upper-triangle blocks written as zeros
// (exp(-1e9 - m) underflows to exactly 0 in fp32, matching reference).
// grid = (kb=32, qb=32, B*H=64), 256 threads.
// ---------------------------------------------------------------------------
__global__ __launch_bounds__(256) void attn_write(float* __restrict__ attn) {
  const int kb = blockIdx.x, qb = blockIdx.y, bh = blockIdx.z;
  const int t = threadIdx.x;
  const int tx = t & 15, ty = t >> 4;
  float* Ab = attn + ((size_t)bh * Sn + qb * 64) * Sn + (size_t)kb * 64;

  if (kb > qb) {
    float4 z = make_float4(0.f, 0.f, 0.f, 0.f);
#pragma unroll
    for (int ii = 0; ii < 4; ii++)
      *(float4*)(Ab + (size_t)((ty << 2) + ii) * Sn + (tx << 2)) = z;
    return;
  }

  const int b = bh >> 4, h = bh & 15;
  __shared__ __align__(16) float Qt[64][64];
  __shared__ __align__(16) float Kt[64][64];

  const float* Qg = g_Q + ((size_t)(b * Sn + qb * 64)) * Dn + h * 64;
  const float* Kg = g_K + ((size_t)(b * Sn + kb * 64)) * Dn + h * 64;
  for (int idx = t; idx < 1024; idx += 256) {
    int row = idx >> 4;
    int dq = (idx & 15) << 2;
    float4 a = *(const float4*)(Qg + (size_t)row * Dn + dq);
    Qt[dq + 0][row] = a.x; Qt[dq + 1][row] = a.y;
    Qt[dq + 2][row] = a.z; Qt[dq + 3][row] = a.w;
    float4 c = *(const float4*)(Kg + (size_t)row * Dn + dq);
    Kt[dq + 0][row] = c.x; Kt[dq + 1][row] = c.y;
    Kt[dq + 2][row] = c.z; Kt[dq + 3][row] = c.w;
  }
  __syncthreads();

  float s[4][4] = {};
#pragma unroll 16
  for (int d = 0; d < 64; d++) {
    float qa[4], ka[4];
    *(float4*)qa = *(const float4*)&Qt[d][ty << 2];
    *(float4*)ka = *(const float4*)&Kt[d][tx << 2];
#pragma unroll
    for (int ii = 0; ii < 4; ii++)
#pragma unroll
      for (int jj = 0; jj < 4; jj++)
        s[ii][jj] = fmaf(qa[ii], ka[jj], s[ii][jj]);
  }

  const float scale = 0.125f;
  const int rbase = bh * Sn + qb * 64 + (ty << 2);
  const bool diag = (kb == qb);
#pragma unroll
  for (int ii = 0; ii < 4; ii++) {
    float mi = g_m[rbase + ii];
    float inv = 1.0f / g_l[rbase + ii];
    float o[4];
#pragma unroll
    for (int jj = 0; jj < 4; jj++) {
      bool masked = diag && (((tx << 2) + jj) > ((ty << 2) + ii));
      o[jj] = masked ? 0.f : __expf(s[ii][jj] * scale - mi) * inv;
    }
    *(float4*)(Ab + (size_t)((ty << 2) + ii) * Sn + (tx << 2)) =
        make_float4(o[0], o[1], o[2], o[3]);
  }
}

// ---------------------------------------------------------------------------
// Kernel 4: residual add + LayerNorm.  grid = 8192 rows, 256 threads.
// ---------------------------------------------------------------------------
__global__ __launch_bounds__(256) void ln_kernel(
    const float* __restrict__ res, const float* __restrict__ gamma,
    const float* __restrict__ beta, float* __restrict__ out) {
  const int row = blockIdx.x;
  const int t = threadIdx.x;
  const float4 cv = ((const float4*)(g_ctx + (size_t)row * Dn))[t];
  const float4 rv = ((const float4*)(res + (size_t)row * Dn))[t];
  float x0 = cv.x + rv.x, x1 = cv.y + rv.y, x2 = cv.z + rv.z, x3 = cv.w + rv.w;

  float sum = x0 + x1 + x2 + x3;
  float sq = x0 * x0 + x1 * x1 + x2 * x2 + x3 * x3;
#pragma unroll
  for (int off = 16; off > 0; off >>= 1) {
    sum += __shfl_xor_sync(0xffffffffu, sum, off);
    sq += __shfl_xor_sync(0xffffffffu, sq, off);
  }
  __shared__ float ssum[8], ssq[8];
  const int w = t >> 5, lane = t & 31;
  if (lane == 0) { ssum[w] = sum; ssq[w] = sq; }
  __syncthreads();
  if (w == 0) {
    float a = (lane < 8) ? ssum[lane] : 0.f;
    float b2 = (lane < 8) ? ssq[lane] : 0.f;
#pragma unroll
    for (int off = 4; off > 0; off >>= 1) {
      a += __shfl_xor_sync(0xffffffffu, a, off);
      b2 += __shfl_xor_sync(0xffffffffu, b2, off);
    }
    if (lane == 0) { ssum[0] = a; ssq[0] = b2; }
  }
  __syncthreads();
  const float mean = ssum[0] * (1.0f / 1024.0f);
  const float var = ssq[0] * (1.0f / 1024.0f) - mean * mean;
  const float rstd = rsqrtf(var + 1e-5f);

  const float4 g = ((const float4*)gamma)[t];
  const float4 be = ((const float4*)beta)[t];
  float4 o = make_float4((x0 - mean) * rstd * g.x + be.x,
                         (x1 - mean) * rstd * g.y + be.y,
                         (x2 - mean) * rstd * g.z + be.z,
                         (x3 - mean) * rstd * g.w + be.w);
  ((float4*)(out + (size_t)row * Dn))[t] = o;
}

// ---------------------------------------------------------------------------
// Inputs (metadata order): q, k, v, mask, Wq, Wk, Wv, ln_gamma, ln_beta
// Output: concat(out[B,S,D], attn[B,H,S,S]) as float32.
// mask is exactly tril(ones) broadcast -> causal predicate used directly.
// ---------------------------------------------------------------------------
extern "C" void kernel_launch(void* const* d_in, const int* in_sizes, int n_in,
                              void* d_out, int out_size) {
  const float* q = (const float*)d_in[0];
  const float* k = (const float*)d_in[1];
  const float* v = (const float*)d_in[2];
  // d_in[3] = mask (int32) — causal tril, applied analytically
  const float* Wq = (const float*)d_in[4];
  const float* Wk = (const float*)d_in[5];
  const float* Wv = (const float*)d_in[6];
  const float* gamma = (const float*)d_in[7];
  const float* beta = (const float*)d_in[8];
  float* out = (float*)d_out;

  proj_gemm<<<dim3(16, 128, 3), 256>>>(q, k, v, Wq, Wk, Wv);
  flash_fwd<<<dim3(32, 16, 4), 256>>>();
  if ((size_t)out_size >= OUT_ELEMS + ATTN_ELEMS) {
    attn_write<<<dim3(32, 32, 64), 256>>>(out + OUT_ELEMS);
  }
  ln_kernel<<<Mn, 256>>>(q, gamma, beta, out);
}

// round 2
// speedup vs baseline: 1.0790x; 1.0790x over previous
#include <cuda_runtime.h>
#include <math.h>
#include <stdint.h>

// Problem constants
#define Bn 4
#define Sn 2048
#define Dn 1024
#define Hn 16
#define Mn (Bn * Sn)                            // 8192 rows
#define OUT_ELEMS ((size_t)Mn * Dn)             // 8,388,608
#define ATTN_ELEMS ((size_t)Bn * Hn * Sn * Sn)  // 268,435,456

// Scratch (device globals; no allocations allowed)
__device__ float g_Q[(size_t)Mn * Dn];
__device__ float g_K[(size_t)Mn * Dn];
__device__ float g_V[(size_t)Mn * Dn];
__device__ float g_ctx[(size_t)Mn * Dn];
__device__ float g_m[Bn * Hn * Sn];
__device__ float g_l[Bn * Hn * Sn];

// ---------------------------------------------------------------------------
// Packed f32x2 helpers (FFMA2 path — doubles fp32 FMA rate on sm_103a)
// ---------------------------------------------------------------------------
typedef unsigned long long u64t;

__device__ __forceinline__ u64t pk2(float v) {
  u64t r;
  asm("mov.b64 %0, {%1, %1};" : "=l"(r) : "f"(v));
  return r;
}
__device__ __forceinline__ void fma2(u64t& d, u64t a, u64t b) {
  asm("fma.rn.f32x2 %0, %1, %2, %0;" : "+l"(d) : "l"(a), "l"(b));
}
__device__ __forceinline__ void mul2(u64t& d, u64t a) {
  asm("mul.rn.f32x2 %0, %0, %1;" : "+l"(d) : "l"(a));
}
__device__ __forceinline__ float2 unpk(u64t v) {
  float2 f;
  asm("mov.b64 {%0, %1}, %2;" : "=f"(f.x), "=f"(f.y) : "l"(v));
  return f;
}

// ---------------------------------------------------------------------------
// Kernel 1: QKV projection GEMM.  X[8192,1024] @ W[1024,1024] -> P[8192,1024]
// 128x128 tile, K-tile 16, 256 threads, 8x8 microtile via fma.rn.f32x2.
// grid = (8, 64, 3)  z selects (q,Wq)/(k,Wk)/(v,Wv)
// ---------------------------------------------------------------------------
__global__ __launch_bounds__(256) void proj_gemm(
    const float* __restrict__ q, const float* __restrict__ k,
    const float* __restrict__ v, const float* __restrict__ Wq,
    const float* __restrict__ Wk, const float* __restrict__ Wv) {
  const int which = blockIdx.z;
  const float* X = (which == 0) ? q : (which == 1) ? k : v;
  const float* W = (which == 0) ? Wq : (which == 1) ? Wk : Wv;
  float* P = (which == 0) ? g_Q : (which == 1) ? g_K : g_V;

  __shared__ __align__(16) float As[16 * 132];  // transposed: As[k][m], m<128
  __shared__ __align__(16) float Bs[16 * 132];  // Bs[k][n], n<128

  const int t = threadIdx.x;
  const int tx = t & 15, ty = t >> 4;
  const int m0 = blockIdx.y * 128, n0 = blockIdx.x * 128;

  const int arow = t >> 1, akq = (t & 1) << 3;      // A: 128 rows x 16 k
  const int brow = t >> 4, bcol = (t & 15) << 3;    // B: 16 rows x 128 n

  // prefetch first tile into registers
  float4 pa0 = *(const float4*)(X + (size_t)(m0 + arow) * Dn + akq);
  float4 pa1 = *(const float4*)(X + (size_t)(m0 + arow) * Dn + akq + 4);
  float4 pb0 = *(const float4*)(W + (size_t)brow * Dn + n0 + bcol);
  float4 pb1 = *(const float4*)(W + (size_t)brow * Dn + n0 + bcol + 4);

  u64t acc[8][4];
#pragma unroll
  for (int i = 0; i < 8; i++)
#pragma unroll
    for (int j = 0; j < 4; j++) acc[i][j] = 0ull;

  for (int k0 = 0; k0 < 1024; k0 += 16) {
    // commit prefetched tile to smem
    As[(akq + 0) * 132 + arow] = pa0.x;
    As[(akq + 1) * 132 + arow] = pa0.y;
    As[(akq + 2) * 132 + arow] = pa0.z;
    As[(akq + 3) * 132 + arow] = pa0.w;
    As[(akq + 4) * 132 + arow] = pa1.x;
    As[(akq + 5) * 132 + arow] = pa1.y;
    As[(akq + 6) * 132 + arow] = pa1.z;
    As[(akq + 7) * 132 + arow] = pa1.w;
    *(float4*)&Bs[brow * 132 + bcol] = pb0;
    *(float4*)&Bs[brow * 132 + bcol + 4] = pb1;
    __syncthreads();

    if (k0 + 16 < 1024) {
      pa0 = *(const float4*)(X + (size_t)(m0 + arow) * Dn + k0 + 16 + akq);
      pa1 = *(const float4*)(X + (size_t)(m0 + arow) * Dn + k0 + 16 + akq + 4);
      pb0 = *(const float4*)(W + (size_t)(k0 + 16 + brow) * Dn + n0 + bcol);
      pb1 = *(const float4*)(W + (size_t)(k0 + 16 + brow) * Dn + n0 + bcol + 4);
    }

#pragma unroll
    for (int kk = 0; kk < 16; kk++) {
      float4 af0 = *(const float4*)&As[kk * 132 + (ty << 3)];
      float4 af1 = *(const float4*)&As[kk * 132 + (ty << 3) + 4];
      u64t a[8];
      a[0] = pk2(af0.x); a[1] = pk2(af0.y); a[2] = pk2(af0.z); a[3] = pk2(af0.w);
      a[4] = pk2(af1.x); a[5] = pk2(af1.y); a[6] = pk2(af1.z); a[7] = pk2(af1.w);
      ulonglong2 b0 = *(const ulonglong2*)&Bs[kk * 132 + (tx << 3)];
      ulonglong2 b1 = *(const ulonglong2*)&Bs[kk * 132 + (tx << 3) + 4];
#pragma unroll
      for (int ii = 0; ii < 8; ii++) {
        fma2(acc[ii][0], a[ii], b0.x);
        fma2(acc[ii][1], a[ii], b0.y);
        fma2(acc[ii][2], a[ii], b1.x);
        fma2(acc[ii][3], a[ii], b1.y);
      }
    }
    __syncthreads();
  }

#pragma unroll
  for (int ii = 0; ii < 8; ii++) {
    float2 f0 = unpk(acc[ii][0]), f1 = unpk(acc[ii][1]);
    float2 f2 = unpk(acc[ii][2]), f3 = unpk(acc[ii][3]);
    float* dst = P + (size_t)(m0 + (ty << 3) + ii) * Dn + n0 + (tx << 3);
    *(float4*)dst = make_float4(f0.x, f0.y, f1.x, f1.y);
    *(float4*)(dst + 4) = make_float4(f2.x, f2.y, f3.x, f3.y);
  }
}

// ---------------------------------------------------------------------------
// Kernel 2: flash-style causal attention.
// grid = (32, 16, 4), 64 threads per CTA. BM=BN=64, dk=dv=64.
// 8x8 microtile via fma.rn.f32x2. Dynamic smem: 3*64*68*4 = 52224 B.
// ---------------------------------------------------------------------------
__global__ __launch_bounds__(64) void flash_fwd() {
  extern __shared__ float sm[];
  float* Qt = sm;               // [64][68] transposed [d][i]
  float* KV = sm + 64 * 68;     // [64][68]  K transposed [d][j], then V [j][c]
  float* Ps = sm + 2 * 64 * 68; // [64][68]  P[i][j]

  const int qb = blockIdx.x, h = blockIdx.y, b = blockIdx.z;
  const int t = threadIdx.x;
  const int tx = t & 7, ty = t >> 3;

  const float* Qg = g_Q + ((size_t)(b * Sn + qb * 64)) * Dn + h * 64;
  for (int idx = t; idx < 1024; idx += 64) {
    int row = idx >> 4;
    int dq = (idx & 15) << 2;
    float4 a = *(const float4*)(Qg + (size_t)row * Dn + dq);
    Qt[(dq + 0) * 68 + row] = a.x;
    Qt[(dq + 1) * 68 + row] = a.y;
    Qt[(dq + 2) * 68 + row] = a.z;
    Qt[(dq + 3) * 68 + row] = a.w;
  }

  float m_i[8], l_i[8];
#pragma unroll
  for (int i = 0; i < 8; i++) { m_i[i] = -1e30f; l_i[i] = 0.f; }
  u64t acc[8][4];
#pragma unroll
  for (int i = 0; i < 8; i++)
#pragma unroll
    for (int j = 0; j < 4; j++) acc[i][j] = 0ull;

  const float scale = 0.125f;  // 1/sqrt(64)

  for (int kb = 0; kb <= qb; kb++) {
    __syncthreads();  // prev iter done with KV (as V) and Ps
    const float* Kg = g_K + ((size_t)(b * Sn + kb * 64)) * Dn + h * 64;
    for (int idx = t; idx < 1024; idx += 64) {
      int row = idx >> 4;
      int dq = (idx & 15) << 2;
      float4 a = *(const float4*)(Kg + (size_t)row * Dn + dq);
      KV[(dq + 0) * 68 + row] = a.x;
      KV[(dq + 1) * 68 + row] = a.y;
      KV[(dq + 2) * 68 + row] = a.z;
      KV[(dq + 3) * 68 + row] = a.w;
    }
    __syncthreads();

    // s = Q K^T  (packed 8x8 microtile)
    u64t sp[8][4];
#pragma unroll
    for (int i = 0; i < 8; i++)
#pragma unroll
      for (int j = 0; j < 4; j++) sp[i][j] = 0ull;
#pragma unroll 4
    for (int d = 0; d < 64; d++) {
      float4 qa0 = *(const float4*)&Qt[d * 68 + (ty << 3)];
      float4 qa1 = *(const float4*)&Qt[d * 68 + (ty << 3) + 4];
      u64t a[8];
      a[0] = pk2(qa0.x); a[1] = pk2(qa0.y); a[2] = pk2(qa0.z); a[3] = pk2(qa0.w);
      a[4] = pk2(qa1.x); a[5] = pk2(qa1.y); a[6] = pk2(qa1.z); a[7] = pk2(qa1.w);
      ulonglong2 b0 = *(const ulonglong2*)&KV[d * 68 + (tx << 3)];
      ulonglong2 b1 = *(const ulonglong2*)&KV[d * 68 + (tx << 3) + 4];
#pragma unroll
      for (int ii = 0; ii < 8; ii++) {
        fma2(sp[ii][0], a[ii], b0.x);
        fma2(sp[ii][1], a[ii], b0.y);
        fma2(sp[ii][2], a[ii], b1.x);
        fma2(sp[ii][3], a[ii], b1.y);
      }
    }

    float s[8][8];
#pragma unroll
    for (int ii = 0; ii < 8; ii++)
#pragma unroll
      for (int jp = 0; jp < 4; jp++) {
        float2 f = unpk(sp[ii][jp]);
        s[ii][2 * jp] = f.x;
        s[ii][2 * jp + 1] = f.y;
      }

    const bool diag = (kb == qb);
#pragma unroll
    for (int ii = 0; ii < 8; ii++)
#pragma unroll
      for (int jj = 0; jj < 8; jj++) {
        float sv = s[ii][jj] * scale;
        if (diag && ((tx << 3) + jj) > ((ty << 3) + ii)) sv = -1e30f;
        s[ii][jj] = sv;
      }

    float p[8][8];
#pragma unroll
    for (int ii = 0; ii < 8; ii++) {
      float rmax = s[ii][0];
#pragma unroll
      for (int jj = 1; jj < 8; jj++) rmax = fmaxf(rmax, s[ii][jj]);
      rmax = fmaxf(rmax, __shfl_xor_sync(0xffffffffu, rmax, 1, 8));
      rmax = fmaxf(rmax, __shfl_xor_sync(0xffffffffu, rmax, 2, 8));
      rmax = fmaxf(rmax, __shfl_xor_sync(0xffffffffu, rmax, 4, 8));
      float mnew = fmaxf(m_i[ii], rmax);
      float alpha = __expf(m_i[ii] - mnew);
      float rs = 0.f;
#pragma unroll
      for (int jj = 0; jj < 8; jj++) {
        p[ii][jj] = __expf(s[ii][jj] - mnew);
        rs += p[ii][jj];
      }
      rs += __shfl_xor_sync(0xffffffffu, rs, 1, 8);
      rs += __shfl_xor_sync(0xffffffffu, rs, 2, 8);
      rs += __shfl_xor_sync(0xffffffffu, rs, 4, 8);
      l_i[ii] = l_i[ii] * alpha + rs;
      m_i[ii] = mnew;
      u64t al = pk2(alpha);
#pragma unroll
      for (int jp = 0; jp < 4; jp++) mul2(acc[ii][jp], al);
    }

    __syncthreads();  // all threads done reading KV as K-tile
    const float* Vg = g_V + ((size_t)(b * Sn + kb * 64)) * Dn + h * 64;
    for (int idx = t; idx < 1024; idx += 64) {
      int row = idx >> 4;
      int dq = (idx & 15) << 2;
      *(float4*)&KV[row * 68 + dq] = *(const float4*)(Vg + (size_t)row * Dn + dq);
    }
#pragma unroll
    for (int ii = 0; ii < 8; ii++) {
      *(float4*)&Ps[((ty << 3) + ii) * 68 + (tx << 3)] =
          make_float4(p[ii][0], p[ii][1], p[ii][2], p[ii][3]);
      *(float4*)&Ps[((ty << 3) + ii) * 68 + (tx << 3) + 4] =
          make_float4(p[ii][4], p[ii][5], p[ii][6], p[ii][7]);
    }
    __syncthreads();

    // acc += P @ V
#pragma unroll 2
    for (int u = 0; u < 64; u++) {
      ulonglong2 vb0 = *(const ulonglong2*)&KV[u * 68 + (tx << 3)];
      ulonglong2 vb1 = *(const ulonglong2*)&KV[u * 68 + (tx << 3) + 4];
#pragma unroll
      for (int ii = 0; ii < 8; ii++) {
        u64t a = pk2(Ps[((ty << 3) + ii) * 68 + u]);
        fma2(acc[ii][0], a, vb0.x);
        fma2(acc[ii][1], a, vb0.y);
        fma2(acc[ii][2], a, vb1.x);
        fma2(acc[ii][3], a, vb1.y);
      }
    }
  }

  float* Cg = g_ctx + ((size_t)(b * Sn + qb * 64)) * Dn + h * 64;
#pragma unroll
  for (int ii = 0; ii < 8; ii++) {
    float inv = 1.0f / l_i[ii];
    float2 f0 = unpk(acc[ii][0]), f1 = unpk(acc[ii][1]);
    float2 f2 = unpk(acc[ii][2]), f3 = unpk(acc[ii][3]);
    float* dst = Cg + (size_t)((ty << 3) + ii) * Dn + (tx << 3);
    *(float4*)dst = make_float4(f0.x * inv, f0.y * inv, f1.x * inv, f1.y * inv);
    *(float4*)(dst + 4) =
        make_float4(f2.x * inv, f2.y * inv, f3.x * inv, f3.y * inv);
  }
  if (tx == 0) {
    int base = (b * Hn + h) * Sn + qb * 64 + (ty << 3);
#pragma unroll
    for (int ii = 0; ii < 8; ii++) {
      g_m[base + ii] = m_i[ii];
      g_l[base + ii] = l_i[ii];
    }
  }
}

// ---------------------------------------------------------------------------
// Kernel 3: materialize attn[B,H,S,S] = softmax probs (recompute QK^T using
// saved row max m and denominator l). grid = (32, 32, 64), 64 threads.
// ---------------------------------------------------------------------------
__global__ __launch_bounds__(64) void attn_write(float* __restrict__ attn) {
  const int kb = blockIdx.x, qb = blockIdx.y, bh = blockIdx.z;
  const int t = threadIdx.x;
  const int tx = t & 7, ty = t >> 3;
  float* Ab = attn + ((size_t)bh * Sn + qb * 64) * Sn + (size_t)kb * 64;

  if (kb > qb) {
    float4 z = make_float4(0.f, 0.f, 0.f, 0.f);
#pragma unroll
    for (int ii = 0; ii < 8; ii++) {
      float* dst = Ab + (size_t)((ty << 3) + ii) * Sn + (tx << 3);
      *(float4*)dst = z;
      *(float4*)(dst + 4) = z;
    }
    return;
  }

  const int b = bh >> 4, h = bh & 15;
  __shared__ __align__(16) float Qt[64 * 68];
  __shared__ __align__(16) float Kt[64 * 68];

  const float* Qg = g_Q + ((size_t)(b * Sn + qb * 64)) * Dn + h * 64;
  const float* Kg = g_K + ((size_t)(b * Sn + kb * 64)) * Dn + h * 64;
  for (int idx = t; idx < 1024; idx += 64) {
    int row = idx >> 4;
    int dq = (idx & 15) << 2;
    float4 a = *(const float4*)(Qg + (size_t)row * Dn + dq);
    Qt[(dq + 0) * 68 + row] = a.x;
    Qt[(dq + 1) * 68 + row] = a.y;
    Qt[(dq + 2) * 68 + row] = a.z;
    Qt[(dq + 3) * 68 + row] = a.w;
    float4 c = *(const float4*)(Kg + (size_t)row * Dn + dq);
    Kt[(dq + 0) * 68 + row] = c.x;
    Kt[(dq + 1) * 68 + row] = c.y;
    Kt[(dq + 2) * 68 + row] = c.z;
    Kt[(dq + 3) * 68 + row] = c.w;
  }
  __syncthreads();

  u64t sp[8][4];
#pragma unroll
  for (int i = 0; i < 8; i++)
#pragma unroll
    for (int j = 0; j < 4; j++) sp[i][j] = 0ull;
#pragma unroll 4
  for (int d = 0; d < 64; d++) {
    float4 qa0 = *(const float4*)&Qt[d * 68 + (ty << 3)];
    float4 qa1 = *(const float4*)&Qt[d * 68 + (ty << 3) + 4];
    u64t a[8];
    a[0] = pk2(qa0.x); a[1] = pk2(qa0.y); a[2] = pk2(qa0.z); a[3] = pk2(qa0.w);
    a[4] = pk2(qa1.x); a[5] = pk2(qa1.y); a[6] = pk2(qa1.z); a[7] = pk2(qa1.w);
    ulonglong2 b0 = *(const ulonglong2*)&Kt[d * 68 + (tx << 3)];
    ulonglong2 b1 = *(const ulonglong2*)&Kt[d * 68 + (tx << 3) + 4];
#pragma unroll
    for (int ii = 0; ii < 8; ii++) {
      fma2(sp[ii][0], a[ii], b0.x);
      fma2(sp[ii][1], a[ii], b0.y);
      fma2(sp[ii][2], a[ii], b1.x);
      fma2(sp[ii][3], a[ii], b1.y);
    }
  }

  const float scale = 0.125f;
  const int rbase = bh * Sn + qb * 64 + (ty << 3);
  const bool diag = (kb == qb);
#pragma unroll
  for (int ii = 0; ii < 8; ii++) {
    float mi = g_m[rbase + ii];
    float inv = 1.0f / g_l[rbase + ii];
    float s[8];
#pragma unroll
    for (int jp = 0; jp < 4; jp++) {
      float2 f = unpk(sp[ii][jp]);
      s[2 * jp] = f.x;
      s[2 * jp + 1] = f.y;
    }
    float o[8];
#pragma unroll
    for (int jj = 0; jj < 8; jj++) {
      bool masked = diag && (((tx << 3) + jj) > ((ty << 3) + ii));
      o[jj] = masked ? 0.f : __expf(s[jj] * scale - mi) * inv;
    }
    float* dst = Ab + (size_t)((ty << 3) + ii) * Sn + (tx << 3);
    *(float4*)dst = make_float4(o[0], o[1], o[2], o[3]);
    *(float4*)(dst + 4) = make_float4(o[4], o[5], o[6], o[7]);
  }
}

// ---------------------------------------------------------------------------
// Kernel 4: residual add + LayerNorm.  grid = 8192 rows, 256 threads.
// ---------------------------------------------------------------------------
__global__ __launch_bounds__(256) void ln_kernel(
    const float* __restrict__ res, const float* __restrict__ gamma,
    const float* __restrict__ beta, float* __restrict__ out) {
  const int row = blockIdx.x;
  const int t = threadIdx.x;
  const float4 cv = ((const float4*)(g_ctx + (size_t)row * Dn))[t];
  const float4 rv = ((const float4*)(res + (size_t)row * Dn))[t];
  float x0 = cv.x + rv.x, x1 = cv.y + rv.y, x2 = cv.z + rv.z, x3 = cv.w + rv.w;

  float sum = x0 + x1 + x2 + x3;
  float sq = x0 * x0 + x1 * x1 + x2 * x2 + x3 * x3;
#pragma unroll
  for (int off = 16; off > 0; off >>= 1) {
    sum += __shfl_xor_sync(0xffffffffu, sum, off);
    sq += __shfl_xor_sync(0xffffffffu, sq, off);
  }
  __shared__ float ssum[8], ssq[8];
  const int w = t >> 5, lane = t & 31;
  if (lane == 0) { ssum[w] = sum; ssq[w] = sq; }
  __syncthreads();
  if (w == 0) {
    float a = (lane < 8) ? ssum[lane] : 0.f;
    float b2 = (lane < 8) ? ssq[lane] : 0.f;
#pragma unroll
    for (int off = 4; off > 0; off >>= 1) {
      a += __shfl_xor_sync(0xffffffffu, a, off);
      b2 += __shfl_xor_sync(0xffffffffu, b2, off);
    }
    if (lane == 0) { ssum[0] = a; ssq[0] = b2; }
  }
  __syncthreads();
  const float mean = ssum[0] * (1.0f / 1024.0f);
  const float var = ssq[0] * (1.0f / 1024.0f) - mean * mean;
  const float rstd = rsqrtf(var + 1e-5f);

  const float4 g = ((const float4*)gamma)[t];
  const float4 be = ((const float4*)beta)[t];
  float4 o = make_float4((x0 - mean) * rstd * g.x + be.x,
                         (x1 - mean) * rstd * g.y + be.y,
                         (x2 - mean) * rstd * g.z + be.z,
                         (x3 - mean) * rstd * g.w + be.w);
  ((float4*)(out + (size_t)row * Dn))[t] = o;
}

// ---------------------------------------------------------------------------
// Inputs (metadata order): q, k, v, mask, Wq, Wk, Wv, ln_gamma, ln_beta
// Output: concat(out[B,S,D], attn[B,H,S,S]) as float32.
// ---------------------------------------------------------------------------
extern "C" void kernel_launch(void* const* d_in, const int* in_sizes, int n_in,
                              void* d_out, int out_size) {
  const float* q = (const float*)d_in[0];
  const float* k = (const float*)d_in[1];
  const float* v = (const float*)d_in[2];
  // d_in[3] = mask (int32) — causal tril, applied analytically
  const float* Wq = (const float*)d_in[4];
  const float* Wk = (const float*)d_in[5];
  const float* Wv = (const float*)d_in[6];
  const float* gamma = (const float*)d_in[7];
  const float* beta = (const float*)d_in[8];
  float* out = (float*)d_out;

  const int flash_smem = 3 * 64 * 68 * (int)sizeof(float);  // 52224 B
  cudaFuncSetAttribute(flash_fwd, cudaFuncAttributeMaxDynamicSharedMemorySize,
                       flash_smem);

  proj_gemm<<<dim3(8, 64, 3), 256>>>(q, k, v, Wq, Wk, Wv);
  flash_fwd<<<dim3(32, 16, 4), 64, flash_smem>>>();
  if ((size_t)out_size >= OUT_ELEMS + ATTN_ELEMS) {
    attn_write<<<dim3(32, 32, 64), 64>>>(out + OUT_ELEMS);
  }
  ln_kernel<<<Mn, 256>>>(q, gamma, beta, out);
}